// round 4
// baseline (speedup 1.0000x reference)
#include <cuda_runtime.h>
#include <math.h>
#include <stdint.h>

// Problem constants
#define ANCH        8
#define CLS         2
#define INDIM       1024
#define ROWS_TOTAL  32768          // 64 * 512
#define ROWS_PER_CTA 128
#define NTHREADS    128
#define GRID_MAIN   (ROWS_TOTAL / ROWS_PER_CTA)   // 256
#define CHUNK       64
#define NCHUNK      (INDIM / CHUNK)               // 16
#define XSTRIDE     68                            // padded row stride (floats), %4==0, conflict-free

// deterministic per-block partial sums: [blk*2] = nll sum, [blk*2+1] = valid count
__device__ float g_part[GRID_MAIN * 2];

// Packed fp32x2 FMA (Blackwell; ptxas never emits FFMA2 from C++ — PTX only)
#define FMA2(d, a, b, c) \
    asm("fma.rn.f32x2 %0, %1, %2, %3;" : "=l"(d) : "l"(a), "l"(b), "l"(c))
#define PACK2(o, lo, hi) \
    asm("mov.b64 %0, {%1, %2};" : "=l"(o) : "f"(lo), "f"(hi))
#define UNPACK2(lo, hi, in) \
    asm("mov.b64 {%0, %1}, %2;" : "=f"(lo), "=f"(hi) : "l"(in))

extern __shared__ float smem_dyn[];
// smem layout: W [0, 16384) floats ; X tile [16384, 16384 + 128*68) floats

__global__ __launch_bounds__(NTHREADS) void rpn_main_kernel(
    const float* __restrict__ X,      // (32768, 1024)
    const float* __restrict__ W,      // (1024, 16)
    const float* __restrict__ bias,   // (16,)
    const int*   __restrict__ labels, // (32768, 8)
    float* __restrict__ out,
    int write_full)
{
    float* Ws = smem_dyn;
    float* Xs = smem_dyn + INDIM * (ANCH * CLS);
    const int tid = threadIdx.x;
    const int rowBase = blockIdx.x * ROWS_PER_CTA;

    // Stage whole W (16384 floats = 4096 float4) into smem once.
    {
        const float4* Wg = (const float4*)W;
        float4* Wd = (float4*)Ws;
        #pragma unroll 4
        for (int i = tid; i < 4096; i += NTHREADS) Wd[i] = Wg[i];
    }

    // Accumulators: 8 packed f32x2 = 16 outputs (k pairs: (0,1),(2,3),...)
    unsigned long long acc[8];
    #pragma unroll
    for (int p = 0; p < 8; ++p) acc[p] = 0ull;

    for (int ch = 0; ch < NCHUNK; ++ch) {
        __syncthreads();  // previous compute done (also covers W staging on ch==0)
        // Stage X tile: 128 rows x 64 cols, coalesced gmem reads
        {
            const int d0 = ch * CHUNK;
            #pragma unroll 4
            for (int i = tid; i < ROWS_PER_CTA * (CHUNK / 4); i += NTHREADS) {
                const int r = i >> 4;        // 16 float4 per row
                const int c = i & 15;
                float4 v = *(const float4*)(X + (size_t)(rowBase + r) * INDIM + d0 + c * 4);
                *(float4*)(Xs + r * XSTRIDE + c * 4) = v;
            }
        }
        __syncthreads();

        const float4* xrow = (const float4*)(Xs + tid * XSTRIDE);
        // W rows for this chunk, viewed as 16B pairs-of-u64 (zero repack cost)
        const ulonglong2* wch = (const ulonglong2*)(Ws + (size_t)ch * CHUNK * 16);

        #pragma unroll
        for (int c = 0; c < CHUNK / 4; ++c) {
            const float4 xv = xrow[c];
            #pragma unroll
            for (int j = 0; j < 4; ++j) {
                const float xj = (j == 0) ? xv.x : (j == 1) ? xv.y : (j == 2) ? xv.z : xv.w;
                unsigned long long xx;
                PACK2(xx, xj, xj);
                // W row d: 16 floats = 8 u64 pairs = 4 ulonglong2 (broadcast LDS.128)
                const ulonglong2* wr = wch + (c * 4 + j) * 4;
                const ulonglong2 wA = wr[0], wB = wr[1], wC = wr[2], wD = wr[3];
                FMA2(acc[0], xx, wA.x, acc[0]);
                FMA2(acc[1], xx, wA.y, acc[1]);
                FMA2(acc[2], xx, wB.x, acc[2]);
                FMA2(acc[3], xx, wB.y, acc[3]);
                FMA2(acc[4], xx, wC.x, acc[4]);
                FMA2(acc[5], xx, wC.y, acc[5]);
                FMA2(acc[6], xx, wD.x, acc[6]);
                FMA2(acc[7], xx, wD.y, acc[7]);
            }
        }
    }

    // ---- Fused epilogue: bias, argmax, CE-NLL, masks ----
    float lg[16];
    #pragma unroll
    for (int p = 0; p < 8; ++p) { UNPACK2(lg[2 * p], lg[2 * p + 1], acc[p]); }
    #pragma unroll
    for (int k = 0; k < 16; ++k) lg[k] += __ldg(bias + k);

    const int row = rowBase + tid;
    const int* lab = labels + (size_t)row * ANCH;

    float lsum = 0.f, lcnt = 0.f;
    float pred[ANCH], msk[ANCH];
    #pragma unroll
    for (int a = 0; a < ANCH; ++a) {
        const float l0 = lg[2 * a], l1 = lg[2 * a + 1];
        const int lb = lab[a];
        const bool p1 = (l1 > l0);           // jnp.argmax: first max wins ties -> strict >
        const bool valid = (lb != -1);
        const float m = fmaxf(l0, l1);
        const float lse = m + logf(expf(l0 - m) + expf(l1 - m));
        const float chosen = (lb == 1) ? l1 : l0;   // label clamped to 0 for padding
        if (valid) { lsum += lse - chosen; lcnt += 1.f; }
        pred[a] = p1 ? 1.f : 0.f;
        msk[a]  = (p1 && valid) ? 1.f : 0.f;
    }

    if (write_full) {
        float* outPred = out + 1 + (size_t)row * ANCH;
        float* outMask = out + 1 + (size_t)ROWS_TOTAL * ANCH + (size_t)row * ANCH;
        #pragma unroll
        for (int a = 0; a < ANCH; ++a) { outPred[a] = pred[a]; outMask[a] = msk[a]; }
    }

    // ---- Deterministic block reduction of (nll sum, valid count) ----
    #pragma unroll
    for (int off = 16; off; off >>= 1) {
        lsum += __shfl_down_sync(0xffffffffu, lsum, off);
        lcnt += __shfl_down_sync(0xffffffffu, lcnt, off);
    }
    __shared__ float red[8];
    const int wid = tid >> 5, lid = tid & 31;
    if (lid == 0) { red[wid * 2] = lsum; red[wid * 2 + 1] = lcnt; }
    __syncthreads();
    if (tid == 0) {
        g_part[blockIdx.x * 2]     = red[0] + red[2] + red[4] + red[6];
        g_part[blockIdx.x * 2 + 1] = red[1] + red[3] + red[5] + red[7];
    }
}

__global__ void rpn_finalize_kernel(float* __restrict__ out)
{
    const int t = threadIdx.x;   // 256 threads, one per main block
    float s = g_part[2 * t];
    float c = g_part[2 * t + 1];
    #pragma unroll
    for (int off = 16; off; off >>= 1) {
        s += __shfl_down_sync(0xffffffffu, s, off);
        c += __shfl_down_sync(0xffffffffu, c, off);
    }
    __shared__ float ss[16];
    const int wid = t >> 5, lid = t & 31;
    if (lid == 0) { ss[wid] = s; ss[8 + wid] = c; }
    __syncthreads();
    if (t == 0) {
        float S = 0.f, C = 0.f;
        #pragma unroll
        for (int i = 0; i < 8; ++i) { S += ss[i]; C += ss[8 + i]; }
        out[0] = S / fmaxf(C, 1.f);
    }
}

extern "C" void kernel_launch(void* const* d_in, const int* in_sizes, int n_in,
                              void* d_out, int out_size)
{
    // Map inputs by element count (robust to ordering); sizes are all distinct.
    const float* X = nullptr;
    const float* W = nullptr;
    const float* b = nullptr;
    const int*   lab = nullptr;
    for (int i = 0; i < n_in; ++i) {
        switch (in_sizes[i]) {
            case ROWS_TOTAL * INDIM:        X   = (const float*)d_in[i]; break; // 33554432
            case INDIM * ANCH * CLS:        W   = (const float*)d_in[i]; break; // 16384
            case ANCH * CLS:                b   = (const float*)d_in[i]; break; // 16
            case ROWS_TOTAL * ANCH:         lab = (const int*)  d_in[i]; break; // 262144
            default: break;
        }
    }
    // Positional fallback
    if (!X   && n_in > 0) X   = (const float*)d_in[0];
    if (!W   && n_in > 1) W   = (const float*)d_in[1];
    if (!b   && n_in > 2) b   = (const float*)d_in[2];
    if (!lab && n_in > 3) lab = (const int*)  d_in[3];

    float* out = (float*)d_out;
    const int write_full = (out_size >= 1 + 2 * ROWS_TOTAL * ANCH) ? 1 : 0;

    const size_t smem_bytes = (size_t)(INDIM * ANCH * CLS + ROWS_PER_CTA * XSTRIDE) * sizeof(float); // 100352
    cudaFuncSetAttribute(rpn_main_kernel, cudaFuncAttributeMaxDynamicSharedMemorySize, (int)smem_bytes);

    rpn_main_kernel<<<GRID_MAIN, NTHREADS, smem_bytes>>>(X, W, b, lab, out, write_full);
    rpn_finalize_kernel<<<1, 256>>>(out);
}

// round 7
// speedup vs baseline: 1.6477x; 1.6477x over previous
#include <cuda_runtime.h>
#include <math.h>
#include <stdint.h>

// Problem constants
#define ANCH        8
#define CLS         2
#define INDIM       1024
#define ROWS_TOTAL  32768              // 64 * 512
#define ROWS_PER_CTA 128
#define NTHREADS    128
#define ROWGROUPS   (ROWS_TOTAL / ROWS_PER_CTA)   // 256
#define SPLITS      4
#define DSPLIT      (INDIM / SPLITS)   // 256
#define CHUNK       64
#define NCHUNK_S    (DSPLIT / CHUNK)   // 4
#define XSTRIDE     68                 // padded row stride (floats), conflict-free LDS.128

// Scratch: per-split partial logits, per-rowgroup loss partials, completion counters.
__device__ float g_partial[SPLITS][ROWS_TOTAL][16];   // 8 MB
__device__ float g_lsum[ROWGROUPS];
__device__ float g_lcnt[ROWGROUPS];
__device__ int   g_done[ROWGROUPS];    // zero-initialized; reset in-kernel each launch
__device__ int   g_done2;              // zero-initialized; reset in-kernel each launch

// Packed fp32x2 FMA (Blackwell FFMA2; PTX-only per SASS quickref)
#define FMA2(d, a, b, c) \
    asm("fma.rn.f32x2 %0, %1, %2, %3;" : "=l"(d) : "l"(a), "l"(b), "l"(c))
#define PACK2(o, lo, hi) \
    asm("mov.b64 %0, {%1, %2};" : "=l"(o) : "f"(lo), "f"(hi))
#define UNPACK2(lo, hi, in) \
    asm("mov.b64 {%0, %1}, %2;" : "=f"(lo), "=f"(hi) : "l"(in))

extern __shared__ float smem_dyn[];
// smem: W-slice [0, 4096) floats ; X tile [4096, 4096 + 128*68) floats  => 51200 bytes

__global__ __launch_bounds__(NTHREADS) void rpn_fused_kernel(
    const float* __restrict__ X,      // (32768, 1024)
    const float* __restrict__ W,      // (1024, 16)
    const float* __restrict__ bias,   // (16,)
    const int*   __restrict__ labels, // (32768, 8)
    float* __restrict__ out,
    int write_full)
{
    float* Ws = smem_dyn;                       // 256 x 16
    float* Xs = smem_dyn + DSPLIT * 16;         // 128 x 68
    const int tid = threadIdx.x;
    const int rg  = blockIdx.x;                 // row group 0..255
    const int sp  = blockIdx.y;                 // d split  0..3
    const int rowBase = rg * ROWS_PER_CTA;
    const int row = rowBase + tid;

    // Stage this split's W slice (4096 floats = 1024 float4)
    {
        const float4* Wg = (const float4*)(W + (size_t)sp * DSPLIT * 16);
        float4* Wd = (float4*)Ws;
        #pragma unroll
        for (int i = tid; i < 1024; i += NTHREADS) Wd[i] = Wg[i];
    }

    // Accumulators: 8 packed f32x2 = 16 outputs (k pairs (0,1),(2,3),...)
    unsigned long long acc[8];
    #pragma unroll
    for (int p = 0; p < 8; ++p) acc[p] = 0ull;

    #pragma unroll 1
    for (int ch = 0; ch < NCHUNK_S; ++ch) {
        __syncthreads();  // previous compute done (also covers W staging on ch==0)
        // Stage X tile: 128 rows x 64 cols, coalesced
        {
            const int d0 = sp * DSPLIT + ch * CHUNK;
            #pragma unroll 4
            for (int i = tid; i < ROWS_PER_CTA * (CHUNK / 4); i += NTHREADS) {
                const int r = i >> 4;        // 16 float4 per row
                const int c = i & 15;
                float4 v = *(const float4*)(X + (size_t)(rowBase + r) * INDIM + d0 + c * 4);
                *(float4*)(Xs + r * XSTRIDE + c * 4) = v;
            }
        }
        __syncthreads();

        const float4* xrow = (const float4*)(Xs + tid * XSTRIDE);
        const ulonglong2* wch = (const ulonglong2*)(Ws + (size_t)ch * CHUNK * 16);

        #pragma unroll
        for (int c = 0; c < CHUNK / 4; ++c) {
            const float4 xv = xrow[c];
            #pragma unroll
            for (int j = 0; j < 4; ++j) {
                const float xj = (j == 0) ? xv.x : (j == 1) ? xv.y : (j == 2) ? xv.z : xv.w;
                unsigned long long xx;
                PACK2(xx, xj, xj);
                const ulonglong2* wr = wch + (c * 4 + j) * 4;   // 16 floats = 4x LDS.128 broadcast
                const ulonglong2 wA = wr[0], wB = wr[1], wC = wr[2], wD = wr[3];
                FMA2(acc[0], xx, wA.x, acc[0]);
                FMA2(acc[1], xx, wA.y, acc[1]);
                FMA2(acc[2], xx, wB.x, acc[2]);
                FMA2(acc[3], xx, wB.y, acc[3]);
                FMA2(acc[4], xx, wC.x, acc[4]);
                FMA2(acc[5], xx, wC.y, acc[5]);
                FMA2(acc[6], xx, wD.x, acc[6]);
                FMA2(acc[7], xx, wD.y, acc[7]);
            }
        }
    }

    // ---- Store this split's partial logits (16 floats / row) ----
    float myp[16];
    #pragma unroll
    for (int p = 0; p < 8; ++p) { UNPACK2(myp[2 * p], myp[2 * p + 1], acc[p]); }
    {
        float4* dst = (float4*)g_partial[sp][row];
        dst[0] = make_float4(myp[0],  myp[1],  myp[2],  myp[3]);
        dst[1] = make_float4(myp[4],  myp[5],  myp[6],  myp[7]);
        dst[2] = make_float4(myp[8],  myp[9],  myp[10], myp[11]);
        dst[3] = make_float4(myp[12], myp[13], myp[14], myp[15]);
    }
    __threadfence();          // publish partials (release side)
    __syncthreads();

    // ---- Last CTA of this row group runs the fused epilogue ----
    __shared__ int s_flag;
    if (tid == 0) {
        int old = atomicAdd(&g_done[rg], 1);
        s_flag = (old == SPLITS - 1) ? 1 : 0;
        if (s_flag) g_done[rg] = 0;   // reset for next replay (no other CTA touches it now)
    }
    __syncthreads();
    if (!s_flag) return;
    __threadfence();          // acquire side: other splits' partials now visible

    // Gather: own split from registers, other 3 from gmem
    float lg[16];
    #pragma unroll
    for (int k = 0; k < 16; ++k) lg[k] = myp[k];
    #pragma unroll
    for (int s = 0; s < SPLITS; ++s) {
        if (s == sp) continue;
        const float4* pp = (const float4*)g_partial[s][row];
        const float4 a = pp[0], b2 = pp[1], c2 = pp[2], d2 = pp[3];
        lg[0]  += a.x;  lg[1]  += a.y;  lg[2]  += a.z;  lg[3]  += a.w;
        lg[4]  += b2.x; lg[5]  += b2.y; lg[6]  += b2.z; lg[7]  += b2.w;
        lg[8]  += c2.x; lg[9]  += c2.y; lg[10] += c2.z; lg[11] += c2.w;
        lg[12] += d2.x; lg[13] += d2.y; lg[14] += d2.z; lg[15] += d2.w;
    }
    #pragma unroll
    for (int k = 0; k < 16; ++k) lg[k] += __ldg(bias + k);

    const int* lab = labels + (size_t)row * ANCH;
    float lsum = 0.f, lcnt = 0.f;
    float pred[ANCH], msk[ANCH];
    #pragma unroll
    for (int a = 0; a < ANCH; ++a) {
        const float l0 = lg[2 * a], l1 = lg[2 * a + 1];
        const int lb = lab[a];
        const bool p1 = (l1 > l0);        // jnp.argmax: first max wins ties -> strict >
        const bool valid = (lb != -1);
        const float m = fmaxf(l0, l1);
        const float lse = m + logf(expf(l0 - m) + expf(l1 - m));
        const float chosen = (lb == 1) ? l1 : l0;
        if (valid) { lsum += lse - chosen; lcnt += 1.f; }
        pred[a] = p1 ? 1.f : 0.f;
        msk[a]  = (p1 && valid) ? 1.f : 0.f;
    }

    if (write_full) {
        float* outPred = out + 1 + (size_t)row * ANCH;
        float* outMask = out + 1 + (size_t)ROWS_TOTAL * ANCH + (size_t)row * ANCH;
        #pragma unroll
        for (int a = 0; a < ANCH; ++a) { outPred[a] = pred[a]; outMask[a] = msk[a]; }
    }

    // ---- Deterministic block reduction of (nll sum, valid count) ----
    #pragma unroll
    for (int off = 16; off; off >>= 1) {
        lsum += __shfl_down_sync(0xffffffffu, lsum, off);
        lcnt += __shfl_down_sync(0xffffffffu, lcnt, off);
    }
    __shared__ float red[8];
    const int wid = tid >> 5, lid = tid & 31;
    if (lid == 0) { red[wid * 2] = lsum; red[wid * 2 + 1] = lcnt; }
    __syncthreads();
    if (tid == 0) {
        g_lsum[rg] = red[0] + red[2] + red[4] + red[6];
        g_lcnt[rg] = red[1] + red[3] + red[5] + red[7];
    }
    __threadfence();
    __syncthreads();

    // ---- Last row group computes the final loss ----
    __shared__ int s_flag2;
    if (tid == 0) {
        int old = atomicAdd(&g_done2, 1);
        s_flag2 = (old == ROWGROUPS - 1) ? 1 : 0;
        if (s_flag2) g_done2 = 0;
    }
    __syncthreads();
    if (!s_flag2) return;
    __threadfence();

    float s = g_lsum[tid] + g_lsum[tid + 128];
    float c = g_lcnt[tid] + g_lcnt[tid + 128];
    #pragma unroll
    for (int off = 16; off; off >>= 1) {
        s += __shfl_down_sync(0xffffffffu, s, off);
        c += __shfl_down_sync(0xffffffffu, c, off);
    }
    __shared__ float fs[8];
    if (lid == 0) { fs[wid * 2] = s; fs[wid * 2 + 1] = c; }
    __syncthreads();
    if (tid == 0) {
        const float S = fs[0] + fs[2] + fs[4] + fs[6];
        const float C = fs[1] + fs[3] + fs[5] + fs[7];
        out[0] = S / fmaxf(C, 1.f);
    }
}

extern "C" void kernel_launch(void* const* d_in, const int* in_sizes, int n_in,
                              void* d_out, int out_size)
{
    // Map inputs by element count (robust to ordering); sizes are all distinct.
    const float* X = nullptr;
    const float* W = nullptr;
    const float* b = nullptr;
    const int*   lab = nullptr;
    for (int i = 0; i < n_in; ++i) {
        switch (in_sizes[i]) {
            case ROWS_TOTAL * INDIM:        X   = (const float*)d_in[i]; break; // 33554432
            case INDIM * ANCH * CLS:        W   = (const float*)d_in[i]; break; // 16384
            case ANCH * CLS:                b   = (const float*)d_in[i]; break; // 16
            case ROWS_TOTAL * ANCH:         lab = (const int*)  d_in[i]; break; // 262144
            default: break;
        }
    }
    if (!X   && n_in > 0) X   = (const float*)d_in[0];
    if (!W   && n_in > 1) W   = (const float*)d_in[1];
    if (!b   && n_in > 2) b   = (const float*)d_in[2];
    if (!lab && n_in > 3) lab = (const int*)  d_in[3];

    float* out = (float*)d_out;
    const int write_full = (out_size >= 1 + 2 * ROWS_TOTAL * ANCH) ? 1 : 0;

    const size_t smem_bytes = (size_t)(DSPLIT * 16 + ROWS_PER_CTA * XSTRIDE) * sizeof(float); // 51200
    cudaFuncSetAttribute(rpn_fused_kernel, cudaFuncAttributeMaxDynamicSharedMemorySize, (int)smem_bytes);

    dim3 grid(ROWGROUPS, SPLITS);
    rpn_fused_kernel<<<grid, NTHREADS, smem_bytes>>>(X, W, b, lab, out, write_full);
}